// round 14
// baseline (speedup 1.0000x reference)
#include <cuda_runtime.h>
#include <cuda_bf16.h>

// Single-launch top-10% mask via max-based band + in-block refinement.
// Grid 2048 x 512, __launch_bounds__(512,4) pins regs <=32 (4 blocks/SM ->
// full-rate fused pass; cold refine path may spill, runs on 2 blocks only).
// P0: blocks 0..127 (64/matrix) sample-max over 1/16 prefix -> band
//     [Tlo,Thi) = 0.9*max*(1 -+ 1e-3) (~38 sigma; ~30K candidates).
//     Other blocks spin on g_ready (set once; later waves never spin).
// P1: ALL blocks: fused pass = provisional mask (k>=Tlo -> 1), count
//     k>=Thi, compact band candidates (smem-staged, one global reserve).
// P2: per-matrix arrive barrier (phase-counting, replay-safe); blocks 0/1
//     refine their matrix's candidates ENTIRELY IN-BLOCK (radix narrowing,
//     exact threshold T + residual z, zero k<T, stable argsort tie fixup).
// Any band infeasibility is DETECTED -> exact single-block rescue
// (correctness unconditional regardless of data distribution).

#define TPB      512
#define NBLK     2048
#define NBM      (NBLK / 2)
#define SBLK     128
#define NST      2048
#define CAND_CAP (1u << 19)
#define BLK_CAP  512
#define EPS      1.0e-3f

__device__ unsigned g_maxk[2];
__device__ unsigned g_sdone[2];
__device__ unsigned g_ready[2];
__device__ unsigned g_Tlo[2], g_Thi[2];
__device__ unsigned g_cand_idx[2][CAND_CAP];
__device__ unsigned g_cand_key[2][CAND_CAP];
__device__ unsigned g_cand_cnt[2];
__device__ unsigned g_hiCnt[2];
__device__ unsigned g_fail[2];
__device__ unsigned g_acount[2];
__device__ unsigned g_aphase[2];   // monotone across replays; never reset

__device__ __forceinline__ unsigned abskey(float v) {
    return __float_as_uint(v) & 0x7FFFFFFFu;
}

// Exact single-block rescue over the full matrix (only on detected failure).
__device__ void rescue_block(const float* __restrict__ in, float* __restrict__ dst,
                             int n, unsigned target_top, unsigned* sh) {
    __shared__ unsigned r_lo, r_span, r_rank;
    const int t = threadIdx.x;
    if (t == 0) { r_lo = 0; r_span = 1u << 30; r_rank = (unsigned)n - target_top; }
    __syncthreads();
    while (r_span > 1) {
        unsigned lo = r_lo, span = r_span;
        unsigned s = (span > (unsigned)NST) ? (unsigned)(32 - __clz(span - 1) - 11) : 0u;
        for (int i = t; i < NST; i += TPB) sh[i] = 0;
        __syncthreads();
        for (int i = t; i < n; i += TPB) {
            unsigned d = abskey(in[i]) - lo;
            if (d < span) atomicAdd(&sh[d >> s], 1u);
        }
        __syncthreads();
        if (t == 0) {
            unsigned rank = r_rank, run = 0;
            for (int i = 0; i < NST; i++) {
                unsigned cc = sh[i];
                if (rank < run + cc) { r_lo = lo + ((unsigned)i << s); r_span = 1u << s; r_rank = rank - run; break; }
                run += cc;
            }
        }
        __syncthreads();
    }
    unsigned T = r_lo, z = r_rank;
    for (int i = t; i < n; i += TPB) {
        unsigned k = abskey(in[i]);
        if (k != T) dst[i] = (k > T) ? 1.0f : 0.0f;
    }
    __syncthreads();
    if (t == 0) {
        unsigned seen = 0;
        for (int i = 0; i < n; i++)
            if (abskey(in[i]) == T) { dst[i] = (seen < z) ? 0.0f : 1.0f; seen++; }
    }
    __syncthreads();
}

__global__ void __launch_bounds__(TPB, 4)
mask_kernel(const float4* __restrict__ A, const float4* __restrict__ B,
            float4* __restrict__ out, int n4, int chunk, unsigned target_top) {
    __shared__ unsigned sh[NST];          // hist / rescue scratch
    __shared__ unsigned tot[TPB];         // scan scratch
    __shared__ unsigned sidx[BLK_CAP];
    __shared__ unsigned skey[BLK_CAP];
    __shared__ unsigned sv0, sv1, sv2, sflag;
    const int m = blockIdx.x & 1;
    const int bl = blockIdx.x >> 1;
    const int t = threadIdx.x;
    const int n = n4 * 4;
    const float4* __restrict__ in4 = m ? B : A;
    float4* __restrict__ dst4 = out + (size_t)m * (size_t)n4;
    float* __restrict__ dst1 = (float*)dst4;

    // ---- P0: sample max over 1/16 prefix (blocks 0..127; 64 per matrix) ----
    if (blockIdx.x < SBLK) {
        const int sbl = blockIdx.x >> 1;              // 0..63
        const int beg = sbl * chunk, end = beg + chunk;
        unsigned mk = 0;
        for (int i = beg + t; i < end; i += TPB) {
            float4 v = in4[i];
            mk = max(mk, abskey(v.x));
            mk = max(mk, abskey(v.y));
            mk = max(mk, abskey(v.z));
            mk = max(mk, abskey(v.w));
        }
        for (int off = 16; off > 0; off >>= 1)
            mk = max(mk, __shfl_xor_sync(0xFFFFFFFFu, mk, off));
        if ((t & 31) == 0) tot[t >> 5] = mk;
        __syncthreads();
        if (t == 0) {
            unsigned bm = 0;
            for (int w = 0; w < TPB / 32; w++) bm = max(bm, tot[w]);
            atomicMax(&g_maxk[m], bm);
            __threadfence();
            sflag = (atomicAdd(&g_sdone[m], 1u) == (unsigned)(SBLK / 2 - 1)) ? 1u : 0u;
        }
        __syncthreads();
        if (sflag && t == 0) {
            __threadfence();
            float mv = __uint_as_float(atomicAdd(&g_maxk[m], 0u));
            float c = 0.9f * mv;
            unsigned tlo = abskey(c * (1.0f - EPS));
            unsigned thi = abskey(c * (1.0f + EPS)) + 1u;
            if (thi <= tlo) thi = tlo + 1u;
            g_Tlo[m] = tlo;
            g_Thi[m] = thi;
            __threadfence();
            atomicExch(&g_ready[m], 1u);
        }
    }

    // ---- wait for band (only wave-1 blocks ever actually spin) ----
    if (t == 0) {
        while (*(volatile unsigned*)&g_ready[m] == 0u) __nanosleep(64);
        sv0 = 0; sv2 = 0;
    }
    __syncthreads();
    __threadfence();
    const unsigned Tlo = *(volatile unsigned*)&g_Tlo[m];
    const unsigned Thi = *(volatile unsigned*)&g_Thi[m];

    // ---- P1: fused pass: mask write + hi count + band compaction ----
    {
        unsigned hi = 0;
        const int stride = NBM * TPB;
        int i0 = bl * TPB + t;
        for (int i = i0; i < n4; i += 2 * stride) {
            int i2 = i + stride;
            float4 v0 = in4[i];
            float4 v1 = (i2 < n4) ? in4[i2] : make_float4(0.f, 0.f, 0.f, 0.f);
            float4 r0, r1;
            unsigned b0 = ((unsigned)i) << 2;
            unsigned b1 = ((unsigned)i2) << 2;
            unsigned k;

            k = abskey(v0.x); r0.x = (k >= Tlo) ? 1.0f : 0.0f; hi += (k >= Thi);
            if (k >= Tlo && k < Thi) { unsigned p = atomicAdd(&sv0, 1u); if (p < BLK_CAP) { sidx[p] = b0;     skey[p] = k; } }
            k = abskey(v0.y); r0.y = (k >= Tlo) ? 1.0f : 0.0f; hi += (k >= Thi);
            if (k >= Tlo && k < Thi) { unsigned p = atomicAdd(&sv0, 1u); if (p < BLK_CAP) { sidx[p] = b0 + 1; skey[p] = k; } }
            k = abskey(v0.z); r0.z = (k >= Tlo) ? 1.0f : 0.0f; hi += (k >= Thi);
            if (k >= Tlo && k < Thi) { unsigned p = atomicAdd(&sv0, 1u); if (p < BLK_CAP) { sidx[p] = b0 + 2; skey[p] = k; } }
            k = abskey(v0.w); r0.w = (k >= Tlo) ? 1.0f : 0.0f; hi += (k >= Thi);
            if (k >= Tlo && k < Thi) { unsigned p = atomicAdd(&sv0, 1u); if (p < BLK_CAP) { sidx[p] = b0 + 3; skey[p] = k; } }
            dst4[i] = r0;

            if (i2 < n4) {
                k = abskey(v1.x); r1.x = (k >= Tlo) ? 1.0f : 0.0f; hi += (k >= Thi);
                if (k >= Tlo && k < Thi) { unsigned p = atomicAdd(&sv0, 1u); if (p < BLK_CAP) { sidx[p] = b1;     skey[p] = k; } }
                k = abskey(v1.y); r1.y = (k >= Tlo) ? 1.0f : 0.0f; hi += (k >= Thi);
                if (k >= Tlo && k < Thi) { unsigned p = atomicAdd(&sv0, 1u); if (p < BLK_CAP) { sidx[p] = b1 + 1; skey[p] = k; } }
                k = abskey(v1.z); r1.z = (k >= Tlo) ? 1.0f : 0.0f; hi += (k >= Thi);
                if (k >= Tlo && k < Thi) { unsigned p = atomicAdd(&sv0, 1u); if (p < BLK_CAP) { sidx[p] = b1 + 2; skey[p] = k; } }
                k = abskey(v1.w); r1.w = (k >= Tlo) ? 1.0f : 0.0f; hi += (k >= Thi);
                if (k >= Tlo && k < Thi) { unsigned p = atomicAdd(&sv0, 1u); if (p < BLK_CAP) { sidx[p] = b1 + 3; skey[p] = k; } }
                dst4[i2] = r1;
            }
        }
        for (int off = 16; off > 0; off >>= 1) hi += __shfl_down_sync(0xFFFFFFFFu, hi, off);
        if ((t & 31) == 0 && hi) atomicAdd(&sv2, hi);
        __syncthreads();
        if (t == 0) {
            if (sv2) atomicAdd(&g_hiCnt[m], sv2);
            unsigned c = sv0;
            if (c > BLK_CAP) { atomicExch(&g_fail[m], 1u); c = BLK_CAP; }
            sv0 = c;
            sv1 = atomicAdd(&g_cand_cnt[m], c);
        }
        __syncthreads();
        unsigned c = sv0, bpos = sv1;
        for (unsigned p = t; p < c; p += TPB) {
            unsigned gp = bpos + p;
            if (gp < CAND_CAP) { g_cand_idx[m][gp] = sidx[p]; g_cand_key[m][gp] = skey[p]; }
        }
    }

    // ---- P2: per-matrix arrive barrier (phase-counting, replay-safe) ----
    __threadfence();
    __syncthreads();
    const bool waiter = (bl == 0);
    if (t == 0) {
        unsigned ph = *(volatile unsigned*)&g_aphase[m];
        if (atomicAdd(&g_acount[m], 1u) == (unsigned)NBM - 1u) {
            g_acount[m] = 0;
            __threadfence();
            atomicAdd(&g_aphase[m], 1u);
        } else if (waiter) {
            while (*(volatile unsigned*)&g_aphase[m] == ph) __nanosleep(64);
        }
        __threadfence();
    }
    __syncthreads();
    if (!waiter) return;

    // ---- refine (one block per matrix, entirely in-block) ----
    unsigned cnt_real = *(volatile unsigned*)&g_cand_cnt[m];
    unsigned cnt = min(cnt_real, CAND_CAP);
    unsigned hic = *(volatile unsigned*)&g_hiCnt[m];
    bool bad = (*(volatile unsigned*)&g_fail[m] != 0) || (cnt_real > CAND_CAP) ||
               (hic > target_top) || (target_top - hic > cnt);
    bool zerokeep = (!bad) && (hic == target_top);
    unsigned T = Thi, z = 0;
    const unsigned* __restrict__ keys = g_cand_key[m];
    const unsigned* __restrict__ idxs = g_cand_idx[m];

    if (!bad && !zerokeep) {
        unsigned keep = target_top - hic;
        unsigned rank = cnt - keep;            // ascending in-band rank
        unsigned lo = Tlo, span = Thi - Tlo;
        while (span > 1) {
            unsigned s = (span > (unsigned)NST) ? (unsigned)(32 - __clz(span - 1) - 11) : 0u;
            for (int i = t; i < NST; i += TPB) sh[i] = 0;
            __syncthreads();
            for (unsigned c = t; c < cnt; c += TPB) {
                unsigned d = keys[c] - lo;
                if (d < span) atomicAdd(&sh[d >> s], 1u);
            }
            __syncthreads();
            unsigned loc[4], sum = 0;
            #pragma unroll
            for (int i = 0; i < 4; i++) { loc[i] = sh[t * 4 + i]; sum += loc[i]; }
            tot[t] = sum;
            __syncthreads();
            for (int off = 1; off < TPB; off <<= 1) {
                unsigned x = (t >= off) ? tot[t - off] : 0u;
                __syncthreads();
                tot[t] += x;
                __syncthreads();
            }
            unsigned run = tot[t] - sum;
            #pragma unroll
            for (int i = 0; i < 4; i++) {
                if (run <= rank && rank < run + loc[i]) { sv0 = (unsigned)(t * 4 + i); sv1 = rank - run; }
                run += loc[i];
            }
            __syncthreads();
            lo += sv0 << s;
            span = 1u << s;
            rank = sv1;
            __syncthreads();
        }
        T = lo;
        z = rank;
    }

    if (!bad) {
        // final candidate pass: zero k<T, collect equals into sidx
        if (t == 0) sv0 = 0;
        __syncthreads();
        for (unsigned c = t; c < cnt; c += TPB) {
            unsigned k = keys[c];
            if (k < T) {
                dst1[idxs[c]] = 0.0f;
            } else if (k == T) {
                unsigned p = atomicAdd(&sv0, 1u);
                if (p < BLK_CAP) sidx[p] = idxs[c];
            }
        }
        __syncthreads();
        unsigned eq = sv0;
        if (eq > BLK_CAP) {
            bad = true;
        } else {
            // stable argsort tie fixup: zero the first z equals by flat index
            for (unsigned e = t; e < eq; e += TPB) {
                unsigned idx = sidx[e];
                unsigned c2 = 0;
                for (unsigned q = 0; q < eq; q++) c2 += (sidx[q] < idx) ? 1u : 0u;
                if (c2 < z) dst1[idx] = 0.0f;
            }
        }
    }
    if (bad) {
        __syncthreads();
        rescue_block((const float*)in4, dst1, n, target_top, sh);
    }

    // ---- cleanup for next graph replay ----
    __syncthreads();
    if (t == 0) {
        g_maxk[m] = 0;
        g_sdone[m] = 0;
        g_ready[m] = 0;
        g_cand_cnt[m] = 0;
        g_hiCnt[m] = 0;
        g_fail[m] = 0;
    }
}

extern "C" void kernel_launch(void* const* d_in, const int* in_sizes, int n_in,
                              void* d_out, int out_size) {
    const float* A = (const float*)d_in[0];
    const float* B = (const float*)d_in[1];
    float* out = (float*)d_out;

    int n = in_sizes[0];
    int n4 = n / 4;
    unsigned j = (unsigned)((1.0 - 0.1) * (double)n);  // mirrors int((1-k)*n)
    unsigned target_top = (unsigned)n - j;             // # of ones
    int chunk = (n4 / 16) / (SBLK / 2);                // float4s per sample block

    mask_kernel<<<NBLK, TPB>>>((const float4*)A, (const float4*)B, (float4*)out,
                               n4, chunk, target_top);
}

// round 15
// speedup vs baseline: 1.1551x; 1.1551x over previous
#include <cuda_runtime.h>
#include <cuda_bf16.h>

// Three-launch top-10% mask. No in-kernel cross-block synchronization.
// K1 (296x512): sample max |x| over the 1/16 prefix of each matrix ->
//     atomicMax into g_maxk[m].  (~3us)
// K2 (2048x512): each block derives band [Tlo,Thi) = 0.9*max*(1 -+ 1e-3)
//     from g_maxk (pure function -> identical across blocks). Fused pass:
//     provisional mask (k>=Tlo -> 1), count k>=Thi, compact band
//     candidates (~30K/matrix). This is the R6-proven 44us loop.
// K3 (2x1024): per-matrix in-block refinement: radix narrowing over the
//     candidates -> exact threshold key T + residual z; zero k<T; stable
//     argsort tie fixup (zero first z equals by ascending flat index);
//     resets state for graph replay. Any band infeasibility is DETECTED
//     (fail flag / count checks) -> exact single-block rescue
//     (correctness unconditional for any input distribution).

#define TPB      512
#define NSB      296
#define NFB      2048
#define NST      2048
#define CAND_CAP (1u << 19)
#define BLK_CAP  512
#define EQ_CAP   2048
#define EPS      1.0e-3f

__device__ unsigned g_maxk[2];
__device__ unsigned g_cand_idx[2][CAND_CAP];
__device__ unsigned g_cand_key[2][CAND_CAP];
__device__ unsigned g_cand_cnt[2];
__device__ unsigned g_hiCnt[2];
__device__ unsigned g_fail[2];

__device__ __forceinline__ unsigned abskey(float v) {
    return __float_as_uint(v) & 0x7FFFFFFFu;
}

// Band derivation: pure function of the sampled max (identical everywhere).
__device__ __forceinline__ void band_from_max(unsigned mk, unsigned* tlo, unsigned* thi) {
    float mv = __uint_as_float(mk);
    float c = 0.9f * mv;
    unsigned lo = abskey(c * (1.0f - EPS));
    unsigned hi = abskey(c * (1.0f + EPS)) + 1u;
    if (hi <= lo) hi = lo + 1u;
    *tlo = lo;
    *thi = hi;
}

// ---------------- K1: sample max ----------------
__global__ void sample_kernel(const float4* __restrict__ A,
                              const float4* __restrict__ B, int n4s) {
    __shared__ unsigned wmax[TPB / 32];
    const int m = blockIdx.x & 1;
    const float4* __restrict__ in = m ? B : A;
    const int t = threadIdx.x;
    unsigned mk = 0;
    int stride = (NSB / 2) * TPB;
    for (int i = (blockIdx.x >> 1) * TPB + t; i < n4s; i += stride) {
        float4 v = in[i];
        mk = max(mk, abskey(v.x));
        mk = max(mk, abskey(v.y));
        mk = max(mk, abskey(v.z));
        mk = max(mk, abskey(v.w));
    }
    for (int off = 16; off > 0; off >>= 1)
        mk = max(mk, __shfl_xor_sync(0xFFFFFFFFu, mk, off));
    if ((t & 31) == 0) wmax[t >> 5] = mk;
    __syncthreads();
    if (t == 0) {
        unsigned bm = 0;
        for (int w = 0; w < TPB / 32; w++) bm = max(bm, wmax[w]);
        atomicMax(&g_maxk[m], bm);
    }
}

// ---------------- K2: fused mask + compaction ----------------
__global__ void fused_kernel(const float4* __restrict__ A,
                             const float4* __restrict__ B,
                             float4* __restrict__ out, int n4) {
    __shared__ unsigned s_idx[BLK_CAP];
    __shared__ unsigned s_key[BLK_CAP];
    __shared__ unsigned s_cnt, s_base, s_hi;
    if (threadIdx.x == 0) { s_cnt = 0; s_hi = 0; }
    __syncthreads();
    const int m = blockIdx.x & 1;
    unsigned Tlo, Thi;
    band_from_max(g_maxk[m], &Tlo, &Thi);
    const float4* __restrict__ in = m ? B : A;
    float4* __restrict__ dst = out + (size_t)m * (size_t)n4;
    unsigned hi = 0;
    const int stride = (gridDim.x >> 1) * blockDim.x;
    int i0 = (blockIdx.x >> 1) * blockDim.x + threadIdx.x;
    for (int i = i0; i < n4; i += 2 * stride) {
        int i2 = i + stride;
        float4 v0 = in[i];
        float4 v1 = (i2 < n4) ? in[i2] : make_float4(0.f, 0.f, 0.f, 0.f);
        float4 r0, r1;
        unsigned b0 = ((unsigned)i) << 2;
        unsigned b1 = ((unsigned)i2) << 2;
        unsigned k;

        k = abskey(v0.x); r0.x = (k >= Tlo) ? 1.0f : 0.0f; hi += (k >= Thi);
        if (k >= Tlo && k < Thi) { unsigned p = atomicAdd(&s_cnt, 1u); if (p < BLK_CAP) { s_idx[p] = b0;     s_key[p] = k; } }
        k = abskey(v0.y); r0.y = (k >= Tlo) ? 1.0f : 0.0f; hi += (k >= Thi);
        if (k >= Tlo && k < Thi) { unsigned p = atomicAdd(&s_cnt, 1u); if (p < BLK_CAP) { s_idx[p] = b0 + 1; s_key[p] = k; } }
        k = abskey(v0.z); r0.z = (k >= Tlo) ? 1.0f : 0.0f; hi += (k >= Thi);
        if (k >= Tlo && k < Thi) { unsigned p = atomicAdd(&s_cnt, 1u); if (p < BLK_CAP) { s_idx[p] = b0 + 2; s_key[p] = k; } }
        k = abskey(v0.w); r0.w = (k >= Tlo) ? 1.0f : 0.0f; hi += (k >= Thi);
        if (k >= Tlo && k < Thi) { unsigned p = atomicAdd(&s_cnt, 1u); if (p < BLK_CAP) { s_idx[p] = b0 + 3; s_key[p] = k; } }
        dst[i] = r0;

        if (i2 < n4) {
            k = abskey(v1.x); r1.x = (k >= Tlo) ? 1.0f : 0.0f; hi += (k >= Thi);
            if (k >= Tlo && k < Thi) { unsigned p = atomicAdd(&s_cnt, 1u); if (p < BLK_CAP) { s_idx[p] = b1;     s_key[p] = k; } }
            k = abskey(v1.y); r1.y = (k >= Tlo) ? 1.0f : 0.0f; hi += (k >= Thi);
            if (k >= Tlo && k < Thi) { unsigned p = atomicAdd(&s_cnt, 1u); if (p < BLK_CAP) { s_idx[p] = b1 + 1; s_key[p] = k; } }
            k = abskey(v1.z); r1.z = (k >= Tlo) ? 1.0f : 0.0f; hi += (k >= Thi);
            if (k >= Tlo && k < Thi) { unsigned p = atomicAdd(&s_cnt, 1u); if (p < BLK_CAP) { s_idx[p] = b1 + 2; s_key[p] = k; } }
            k = abskey(v1.w); r1.w = (k >= Tlo) ? 1.0f : 0.0f; hi += (k >= Thi);
            if (k >= Tlo && k < Thi) { unsigned p = atomicAdd(&s_cnt, 1u); if (p < BLK_CAP) { s_idx[p] = b1 + 3; s_key[p] = k; } }
            dst[i2] = r1;
        }
    }
    for (int off = 16; off > 0; off >>= 1) hi += __shfl_down_sync(0xFFFFFFFFu, hi, off);
    if ((threadIdx.x & 31) == 0 && hi) atomicAdd(&s_hi, hi);
    __syncthreads();
    if (threadIdx.x == 0) {
        if (s_hi) atomicAdd(&g_hiCnt[m], s_hi);
        unsigned c = s_cnt;
        if (c > BLK_CAP) { atomicExch(&g_fail[m], 1u); c = BLK_CAP; }
        s_cnt = c;
        s_base = atomicAdd(&g_cand_cnt[m], c);
    }
    __syncthreads();
    unsigned c = s_cnt, bpos = s_base;
    for (unsigned p = threadIdx.x; p < c; p += blockDim.x) {
        unsigned gp = bpos + p;
        if (gp < CAND_CAP) { g_cand_idx[m][gp] = s_idx[p]; g_cand_key[m][gp] = s_key[p]; }
    }
}

// ---------------- K3: in-block refinement ----------------
// Exact single-block rescue over the full matrix (only on detected failure).
__device__ void rescue_block(const float* __restrict__ in, float* __restrict__ dst,
                             int n, unsigned target_top, unsigned* sh) {
    __shared__ unsigned r_lo, r_span, r_rank;
    const int t = threadIdx.x;
    if (t == 0) { r_lo = 0; r_span = 1u << 30; r_rank = (unsigned)n - target_top; }
    __syncthreads();
    while (r_span > 1) {
        unsigned lo = r_lo, span = r_span;
        unsigned s = (span > (unsigned)NST) ? (unsigned)(32 - __clz(span - 1) - 11) : 0u;
        for (int i = t; i < NST; i += 1024) sh[i] = 0;
        __syncthreads();
        for (int i = t; i < n; i += 1024) {
            unsigned d = abskey(in[i]) - lo;
            if (d < span) atomicAdd(&sh[d >> s], 1u);
        }
        __syncthreads();
        if (t == 0) {
            unsigned rank = r_rank, run = 0;
            for (int i = 0; i < NST; i++) {
                unsigned cc = sh[i];
                if (rank < run + cc) { r_lo = lo + ((unsigned)i << s); r_span = 1u << s; r_rank = rank - run; break; }
                run += cc;
            }
        }
        __syncthreads();
    }
    unsigned T = r_lo, z = r_rank;
    for (int i = t; i < n; i += 1024) {
        unsigned k = abskey(in[i]);
        if (k != T) dst[i] = (k > T) ? 1.0f : 0.0f;
    }
    __syncthreads();
    if (t == 0) {
        unsigned seen = 0;
        for (int i = 0; i < n; i++)
            if (abskey(in[i]) == T) { dst[i] = (seen < z) ? 0.0f : 1.0f; seen++; }
    }
    __syncthreads();
}

__global__ void __launch_bounds__(1024)
refine_kernel(const float* __restrict__ A, const float* __restrict__ B,
              float* __restrict__ out, int n, unsigned target_top) {
    __shared__ unsigned sh[NST];
    __shared__ unsigned tot[1024];
    __shared__ unsigned sidx[EQ_CAP];
    __shared__ unsigned sv0, sv1;
    const int m = blockIdx.x;
    const int t = threadIdx.x;
    const float* __restrict__ in1 = m ? B : A;
    float* __restrict__ dst = out + (size_t)m * (size_t)n;

    unsigned Tlo, Thi;
    band_from_max(g_maxk[m], &Tlo, &Thi);

    unsigned cnt_real = g_cand_cnt[m];
    unsigned cnt = min(cnt_real, CAND_CAP);
    unsigned hic = g_hiCnt[m];
    bool bad = (g_fail[m] != 0) || (cnt_real > CAND_CAP) ||
               (hic > target_top) || (target_top - hic > cnt);
    if (!bad && (Thi - Tlo) > (1u << 22)) bad = true;
    bool zerokeep = (!bad) && (hic == target_top);
    unsigned T = Thi, z = 0;
    const unsigned* __restrict__ keys = g_cand_key[m];
    const unsigned* __restrict__ idxs = g_cand_idx[m];

    if (!bad && !zerokeep) {
        unsigned keep = target_top - hic;
        unsigned rank = cnt - keep;            // ascending in-band rank
        unsigned lo = Tlo, span = Thi - Tlo;
        while (span > 1) {
            unsigned s = (span > (unsigned)NST) ? (unsigned)(32 - __clz(span - 1) - 11) : 0u;
            for (int i = t; i < NST; i += 1024) sh[i] = 0;
            __syncthreads();
            for (unsigned c = t; c < cnt; c += 1024) {
                unsigned d = keys[c] - lo;
                if (d < span) atomicAdd(&sh[d >> s], 1u);
            }
            __syncthreads();
            unsigned l0 = sh[2 * t], l1 = sh[2 * t + 1];
            unsigned sum = l0 + l1;
            tot[t] = sum;
            __syncthreads();
            for (int off = 1; off < 1024; off <<= 1) {
                unsigned x = (t >= off) ? tot[t - off] : 0u;
                __syncthreads();
                tot[t] += x;
                __syncthreads();
            }
            unsigned run = tot[t] - sum;
            if (run <= rank && rank < run + l0)            { sv0 = 2u * t;     sv1 = rank - run; }
            else if (run + l0 <= rank && rank < run + sum) { sv0 = 2u * t + 1; sv1 = rank - run - l0; }
            __syncthreads();
            lo += sv0 << s;
            span = 1u << s;
            rank = sv1;
            __syncthreads();
        }
        T = lo;
        z = rank;
    }

    if (!bad) {
        // final candidate pass: zero k<T, collect equals
        if (t == 0) sv0 = 0;
        __syncthreads();
        for (unsigned c = t; c < cnt; c += 1024) {
            unsigned k = keys[c];
            if (k < T) {
                dst[idxs[c]] = 0.0f;
            } else if (k == T) {
                unsigned p = atomicAdd(&sv0, 1u);
                if (p < EQ_CAP) sidx[p] = idxs[c];
            }
        }
        __syncthreads();
        unsigned eq = sv0;
        if (eq > EQ_CAP) {
            bad = true;
        } else {
            // stable argsort tie fixup: zero first z equals by flat index
            for (unsigned e = t; e < eq; e += 1024) {
                unsigned idx = sidx[e];
                unsigned c2 = 0;
                for (unsigned q = 0; q < eq; q++) c2 += (sidx[q] < idx) ? 1u : 0u;
                if (c2 < z) dst[idx] = 0.0f;
            }
        }
    }
    if (bad) {
        __syncthreads();
        rescue_block(in1, dst, n, target_top, sh);
    }

    // reset state for the next graph replay
    __syncthreads();
    if (t == 0) {
        g_maxk[m] = 0;
        g_cand_cnt[m] = 0;
        g_hiCnt[m] = 0;
        g_fail[m] = 0;
    }
}

extern "C" void kernel_launch(void* const* d_in, const int* in_sizes, int n_in,
                              void* d_out, int out_size) {
    const float* A = (const float*)d_in[0];
    const float* B = (const float*)d_in[1];
    float* out = (float*)d_out;

    int n = in_sizes[0];
    int n4 = n / 4;
    int n4s = n4 / 16;                                  // 1/16 sample prefix
    unsigned j = (unsigned)((1.0 - 0.1) * (double)n);   // mirrors int((1-k)*n)
    unsigned target_top = (unsigned)n - j;              // # of ones

    sample_kernel<<<NSB, TPB>>>((const float4*)A, (const float4*)B, n4s);
    fused_kernel<<<2048, TPB>>>((const float4*)A, (const float4*)B,
                                (float4*)out, n4);
    refine_kernel<<<2, 1024>>>(A, B, out, n, target_top);
}

// round 16
// speedup vs baseline: 1.3795x; 1.1943x over previous
#include <cuda_runtime.h>
#include <cuda_bf16.h>

// Three-launch top-10% mask. No in-kernel cross-block synchronization.
// K1 (296x512, ~2us): sample max |x| over a 1/64 prefix -> atomicMax g_maxk.
// K2 (2048x512, __launch_bounds__(512,4) pins 32 regs -> 4 blk/SM): each
//     block derives band [Tlo,Thi) = 0.9*max*(1 -+ 1e-3) from g_maxk (pure
//     function, identical everywhere). Fused pass: provisional mask
//     (k>=Tlo -> 1), count k>=Thi, compact band candidates (~30K/matrix).
// K3 (2x1024): per-matrix in-block refinement: radix narrowing over the
//     candidates -> exact threshold key T + residual z; zero k<T; stable
//     argsort tie fixup (zero first z equals by ascending flat index);
//     resets state for graph replay. Any band infeasibility is DETECTED
//     (fail flag / count checks) -> exact single-block rescue
//     (correctness unconditional for any input distribution).

#define TPB      512
#define NSB      296
#define NST      2048
#define CAND_CAP (1u << 19)
#define BLK_CAP  512
#define EQ_CAP   2048
#define EPS      1.0e-3f

__device__ unsigned g_maxk[2];
__device__ unsigned g_cand_idx[2][CAND_CAP];
__device__ unsigned g_cand_key[2][CAND_CAP];
__device__ unsigned g_cand_cnt[2];
__device__ unsigned g_hiCnt[2];
__device__ unsigned g_fail[2];

__device__ __forceinline__ unsigned abskey(float v) {
    return __float_as_uint(v) & 0x7FFFFFFFu;
}

// Band derivation: pure function of the sampled max (identical everywhere).
__device__ __forceinline__ void band_from_max(unsigned mk, unsigned* tlo, unsigned* thi) {
    float mv = __uint_as_float(mk);
    float c = 0.9f * mv;
    unsigned lo = abskey(c * (1.0f - EPS));
    unsigned hi = abskey(c * (1.0f + EPS)) + 1u;
    if (hi <= lo) hi = lo + 1u;
    *tlo = lo;
    *thi = hi;
}

// ---------------- K1: sample max (1/64 of each matrix) ----------------
__global__ void sample_kernel(const float4* __restrict__ A,
                              const float4* __restrict__ B, int n4s) {
    __shared__ unsigned wmax[TPB / 32];
    const int m = blockIdx.x & 1;
    const float4* __restrict__ in = m ? B : A;
    const int t = threadIdx.x;
    unsigned mk = 0;
    int stride = (NSB / 2) * TPB;
    for (int i = (blockIdx.x >> 1) * TPB + t; i < n4s; i += stride) {
        float4 v = in[i];
        mk = max(mk, abskey(v.x));
        mk = max(mk, abskey(v.y));
        mk = max(mk, abskey(v.z));
        mk = max(mk, abskey(v.w));
    }
    for (int off = 16; off > 0; off >>= 1)
        mk = max(mk, __shfl_xor_sync(0xFFFFFFFFu, mk, off));
    if ((t & 31) == 0) wmax[t >> 5] = mk;
    __syncthreads();
    if (t == 0) {
        unsigned bm = 0;
        for (int w = 0; w < TPB / 32; w++) bm = max(bm, wmax[w]);
        atomicMax(&g_maxk[m], bm);
    }
}

// ---------------- K2: fused mask + compaction ----------------
__global__ void __launch_bounds__(TPB, 4)
fused_kernel(const float4* __restrict__ A,
             const float4* __restrict__ B,
             float4* __restrict__ out, int n4) {
    __shared__ unsigned s_idx[BLK_CAP];
    __shared__ unsigned s_key[BLK_CAP];
    __shared__ unsigned s_cnt, s_base, s_hi;
    if (threadIdx.x == 0) { s_cnt = 0; s_hi = 0; }
    __syncthreads();
    const int m = blockIdx.x & 1;
    unsigned Tlo, Thi;
    band_from_max(g_maxk[m], &Tlo, &Thi);
    const unsigned W = Thi - Tlo;            // band width (one-compare check)
    const float4* __restrict__ in = m ? B : A;
    float4* __restrict__ dst = out + (size_t)m * (size_t)n4;
    unsigned hi = 0;
    const int stride = (gridDim.x >> 1) * blockDim.x;
    int i0 = (blockIdx.x >> 1) * blockDim.x + threadIdx.x;
    for (int i = i0; i < n4; i += 2 * stride) {
        int i2 = i + stride;
        float4 v0 = in[i];
        float4 v1 = (i2 < n4) ? in[i2] : make_float4(0.f, 0.f, 0.f, 0.f);
        float4 r0, r1;
        unsigned b0 = ((unsigned)i) << 2;
        unsigned b1 = ((unsigned)i2) << 2;
        unsigned k, d;

        k = abskey(v0.x); d = k - Tlo; r0.x = (k >= Tlo) ? 1.0f : 0.0f; hi += (k >= Thi);
        if (d < W) { unsigned p = atomicAdd(&s_cnt, 1u); if (p < BLK_CAP) { s_idx[p] = b0;     s_key[p] = k; } }
        k = abskey(v0.y); d = k - Tlo; r0.y = (k >= Tlo) ? 1.0f : 0.0f; hi += (k >= Thi);
        if (d < W) { unsigned p = atomicAdd(&s_cnt, 1u); if (p < BLK_CAP) { s_idx[p] = b0 + 1; s_key[p] = k; } }
        k = abskey(v0.z); d = k - Tlo; r0.z = (k >= Tlo) ? 1.0f : 0.0f; hi += (k >= Thi);
        if (d < W) { unsigned p = atomicAdd(&s_cnt, 1u); if (p < BLK_CAP) { s_idx[p] = b0 + 2; s_key[p] = k; } }
        k = abskey(v0.w); d = k - Tlo; r0.w = (k >= Tlo) ? 1.0f : 0.0f; hi += (k >= Thi);
        if (d < W) { unsigned p = atomicAdd(&s_cnt, 1u); if (p < BLK_CAP) { s_idx[p] = b0 + 3; s_key[p] = k; } }
        dst[i] = r0;

        if (i2 < n4) {
            k = abskey(v1.x); d = k - Tlo; r1.x = (k >= Tlo) ? 1.0f : 0.0f; hi += (k >= Thi);
            if (d < W) { unsigned p = atomicAdd(&s_cnt, 1u); if (p < BLK_CAP) { s_idx[p] = b1;     s_key[p] = k; } }
            k = abskey(v1.y); d = k - Tlo; r1.y = (k >= Tlo) ? 1.0f : 0.0f; hi += (k >= Thi);
            if (d < W) { unsigned p = atomicAdd(&s_cnt, 1u); if (p < BLK_CAP) { s_idx[p] = b1 + 1; s_key[p] = k; } }
            k = abskey(v1.z); d = k - Tlo; r1.z = (k >= Tlo) ? 1.0f : 0.0f; hi += (k >= Thi);
            if (d < W) { unsigned p = atomicAdd(&s_cnt, 1u); if (p < BLK_CAP) { s_idx[p] = b1 + 2; s_key[p] = k; } }
            k = abskey(v1.w); d = k - Tlo; r1.w = (k >= Tlo) ? 1.0f : 0.0f; hi += (k >= Thi);
            if (d < W) { unsigned p = atomicAdd(&s_cnt, 1u); if (p < BLK_CAP) { s_idx[p] = b1 + 3; s_key[p] = k; } }
            dst[i2] = r1;
        }
    }
    for (int off = 16; off > 0; off >>= 1) hi += __shfl_down_sync(0xFFFFFFFFu, hi, off);
    if ((threadIdx.x & 31) == 0 && hi) atomicAdd(&s_hi, hi);
    __syncthreads();
    if (threadIdx.x == 0) {
        if (s_hi) atomicAdd(&g_hiCnt[m], s_hi);
        unsigned c = s_cnt;
        if (c > BLK_CAP) { atomicExch(&g_fail[m], 1u); c = BLK_CAP; }
        s_cnt = c;
        s_base = atomicAdd(&g_cand_cnt[m], c);
    }
    __syncthreads();
    unsigned c = s_cnt, bpos = s_base;
    for (unsigned p = threadIdx.x; p < c; p += blockDim.x) {
        unsigned gp = bpos + p;
        if (gp < CAND_CAP) { g_cand_idx[m][gp] = s_idx[p]; g_cand_key[m][gp] = s_key[p]; }
    }
}

// ---------------- K3: in-block refinement ----------------
// Exact single-block rescue over the full matrix (only on detected failure).
__device__ void rescue_block(const float* __restrict__ in, float* __restrict__ dst,
                             int n, unsigned target_top, unsigned* sh) {
    __shared__ unsigned r_lo, r_span, r_rank;
    const int t = threadIdx.x;
    if (t == 0) { r_lo = 0; r_span = 1u << 30; r_rank = (unsigned)n - target_top; }
    __syncthreads();
    while (r_span > 1) {
        unsigned lo = r_lo, span = r_span;
        unsigned s = (span > (unsigned)NST) ? (unsigned)(32 - __clz(span - 1) - 11) : 0u;
        for (int i = t; i < NST; i += 1024) sh[i] = 0;
        __syncthreads();
        for (int i = t; i < n; i += 1024) {
            unsigned d = abskey(in[i]) - lo;
            if (d < span) atomicAdd(&sh[d >> s], 1u);
        }
        __syncthreads();
        if (t == 0) {
            unsigned rank = r_rank, run = 0;
            for (int i = 0; i < NST; i++) {
                unsigned cc = sh[i];
                if (rank < run + cc) { r_lo = lo + ((unsigned)i << s); r_span = 1u << s; r_rank = rank - run; break; }
                run += cc;
            }
        }
        __syncthreads();
    }
    unsigned T = r_lo, z = r_rank;
    for (int i = t; i < n; i += 1024) {
        unsigned k = abskey(in[i]);
        if (k != T) dst[i] = (k > T) ? 1.0f : 0.0f;
    }
    __syncthreads();
    if (t == 0) {
        unsigned seen = 0;
        for (int i = 0; i < n; i++)
            if (abskey(in[i]) == T) { dst[i] = (seen < z) ? 0.0f : 1.0f; seen++; }
    }
    __syncthreads();
}

__global__ void __launch_bounds__(1024)
refine_kernel(const float* __restrict__ A, const float* __restrict__ B,
              float* __restrict__ out, int n, unsigned target_top) {
    __shared__ unsigned sh[NST];
    __shared__ unsigned tot[1024];
    __shared__ unsigned sidx[EQ_CAP];
    __shared__ unsigned sv0, sv1;
    const int m = blockIdx.x;
    const int t = threadIdx.x;
    const float* __restrict__ in1 = m ? B : A;
    float* __restrict__ dst = out + (size_t)m * (size_t)n;

    unsigned Tlo, Thi;
    band_from_max(g_maxk[m], &Tlo, &Thi);

    unsigned cnt_real = g_cand_cnt[m];
    unsigned cnt = min(cnt_real, CAND_CAP);
    unsigned hic = g_hiCnt[m];
    bool bad = (g_fail[m] != 0) || (cnt_real > CAND_CAP) ||
               (hic > target_top) || (target_top - hic > cnt);
    if (!bad && (Thi - Tlo) > (1u << 22)) bad = true;
    bool zerokeep = (!bad) && (hic == target_top);
    unsigned T = Thi, z = 0;
    const unsigned* __restrict__ keys = g_cand_key[m];
    const unsigned* __restrict__ idxs = g_cand_idx[m];

    if (!bad && !zerokeep) {
        unsigned keep = target_top - hic;
        unsigned rank = cnt - keep;            // ascending in-band rank
        unsigned lo = Tlo, span = Thi - Tlo;
        while (span > 1) {
            unsigned s = (span > (unsigned)NST) ? (unsigned)(32 - __clz(span - 1) - 11) : 0u;
            for (int i = t; i < NST; i += 1024) sh[i] = 0;
            __syncthreads();
            for (unsigned c = t; c < cnt; c += 1024) {
                unsigned d = keys[c] - lo;
                if (d < span) atomicAdd(&sh[d >> s], 1u);
            }
            __syncthreads();
            unsigned l0 = sh[2 * t], l1 = sh[2 * t + 1];
            unsigned sum = l0 + l1;
            tot[t] = sum;
            __syncthreads();
            for (int off = 1; off < 1024; off <<= 1) {
                unsigned x = (t >= off) ? tot[t - off] : 0u;
                __syncthreads();
                tot[t] += x;
                __syncthreads();
            }
            unsigned run = tot[t] - sum;
            if (run <= rank && rank < run + l0)            { sv0 = 2u * t;     sv1 = rank - run; }
            else if (run + l0 <= rank && rank < run + sum) { sv0 = 2u * t + 1; sv1 = rank - run - l0; }
            __syncthreads();
            lo += sv0 << s;
            span = 1u << s;
            rank = sv1;
            __syncthreads();
        }
        T = lo;
        z = rank;
    }

    if (!bad) {
        // final candidate pass: zero k<T, collect equals
        if (t == 0) sv0 = 0;
        __syncthreads();
        for (unsigned c = t; c < cnt; c += 1024) {
            unsigned k = keys[c];
            if (k < T) {
                dst[idxs[c]] = 0.0f;
            } else if (k == T) {
                unsigned p = atomicAdd(&sv0, 1u);
                if (p < EQ_CAP) sidx[p] = idxs[c];
            }
        }
        __syncthreads();
        unsigned eq = sv0;
        if (eq > EQ_CAP) {
            bad = true;
        } else {
            // stable argsort tie fixup: zero first z equals by flat index
            for (unsigned e = t; e < eq; e += 1024) {
                unsigned idx = sidx[e];
                unsigned c2 = 0;
                for (unsigned q = 0; q < eq; q++) c2 += (sidx[q] < idx) ? 1u : 0u;
                if (c2 < z) dst[idx] = 0.0f;
            }
        }
    }
    if (bad) {
        __syncthreads();
        rescue_block(in1, dst, n, target_top, sh);
    }

    // reset state for the next graph replay
    __syncthreads();
    if (t == 0) {
        g_maxk[m] = 0;
        g_cand_cnt[m] = 0;
        g_hiCnt[m] = 0;
        g_fail[m] = 0;
    }
}

extern "C" void kernel_launch(void* const* d_in, const int* in_sizes, int n_in,
                              void* d_out, int out_size) {
    const float* A = (const float*)d_in[0];
    const float* B = (const float*)d_in[1];
    float* out = (float*)d_out;

    int n = in_sizes[0];
    int n4 = n / 4;
    int n4s = n4 / 64;                                  // 1/64 sample prefix
    unsigned j = (unsigned)((1.0 - 0.1) * (double)n);   // mirrors int((1-k)*n)
    unsigned target_top = (unsigned)n - j;              // # of ones

    sample_kernel<<<NSB, TPB>>>((const float4*)A, (const float4*)B, n4s);
    fused_kernel<<<2048, TPB>>>((const float4*)A, (const float4*)B,
                                (float4*)out, n4);
    refine_kernel<<<2, 1024>>>(A, B, out, n, target_top);
}